// round 1
// baseline (speedup 1.0000x reference)
#include <cuda_runtime.h>
#include <math.h>

#define NN 50000
#define EE 800000

// ---------------- scratch (device globals, no runtime alloc) ----------------
__device__ int   g_deg[NN];
__device__ int   g_off[NN + 1];
__device__ int   g_cur[NN];
__device__ float g_dinv[NN];
__device__ int   g_srce[EE];
__device__ float g_ew[EE];

__device__ float g_A [(size_t)NN * 128];  // conv1: [init(64) | root(64)]
__device__ float g_B [(size_t)NN * 64];   // conv1 after t=0
__device__ float g_C [(size_t)NN * 64];   // conv1 after deep matmul
__device__ float g_h [(size_t)NN * 32];   // conv1 output (mean over stacks)
__device__ float g_D [(size_t)NN * 160];  // conv2: [init(80) | root(80)]
__device__ float g_E2[(size_t)NN * 80];   // conv2 after t=0
__device__ float g_F2[(size_t)NN * 80];   // conv2 after deep matmul
__device__ float g_h2[(size_t)NN * 40];   // conv2 output (pre log_softmax)

__device__ float g_Wp1[128 * 128];        // packed [w1_init | w1_root]
__device__ float g_Wd1[64 * 64];          // block-diag w1_deep
__device__ float g_Wp2[32 * 160];         // packed [w2_init | w2_root]
__device__ float g_Wd2[80 * 80];          // block-diag w2_deep

// ---------------- graph preprocessing ----------------
__global__ void zero_deg_kernel() {
    int i = blockIdx.x * blockDim.x + threadIdx.x;
    if (i < NN) g_deg[i] = 0;
}

__global__ void hist_kernel(const int* __restrict__ col) {
    int i = blockIdx.x * blockDim.x + threadIdx.x;
    if (i < EE) atomicAdd(&g_deg[col[i]], 1);
}

__global__ void dinv_kernel() {
    int i = blockIdx.x * blockDim.x + threadIdx.x;
    if (i < NN) {
        int d = g_deg[i];
        g_dinv[i] = (d > 0) ? rsqrtf((float)d) : 0.0f;
    }
}

// single-block exclusive scan of g_deg -> g_off, also seeds g_cur
__global__ void scan_kernel() {
    __shared__ int part[1024];
    const int t = threadIdx.x;
    const int CH = (NN + 1023) / 1024;  // 49
    int base = t * CH;
    int hi = base + CH; if (hi > NN) hi = NN;
    int sum = 0;
    for (int i = base; i < hi; ++i) sum += g_deg[i];
    part[t] = sum;
    __syncthreads();
    // Hillis-Steele inclusive scan (in place, double sync)
    for (int off = 1; off < 1024; off <<= 1) {
        int v = (t >= off) ? part[t - off] : 0;
        __syncthreads();
        part[t] += v;
        __syncthreads();
    }
    int run = part[t] - sum;  // exclusive prefix for this thread's chunk
    for (int i = base; i < hi; ++i) {
        g_off[i] = run;
        g_cur[i] = run;
        run += g_deg[i];
    }
    if (t == 1023) g_off[NN] = part[1023];
}

__global__ void fill_kernel(const int* __restrict__ row, const int* __restrict__ col) {
    int i = blockIdx.x * blockDim.x + threadIdx.x;
    if (i < EE) {
        int r = row[i];
        int c = col[i];
        int pos = atomicAdd(&g_cur[c], 1);
        g_srce[pos] = r;
        g_ew[pos]   = g_dinv[r] * g_dinv[c];
    }
}

// ---------------- weight packing ----------------
__global__ void prep_kernel(const float* __restrict__ w1i, const float* __restrict__ w1d,
                            const float* __restrict__ w1r, const float* __restrict__ w2i,
                            const float* __restrict__ w2d, const float* __restrict__ w2r) {
    int i = blockIdx.x * blockDim.x + threadIdx.x;
    if (i < 16384) {                       // Wp1 : 128 x 128
        int f = i >> 7, j = i & 127;
        float v;
        if (j < 64) { int k = j >> 5, h = j & 31; v = w1i[(k * 128 + f) * 32 + h]; }
        else        { int j2 = j - 64; int k = j2 >> 5, h = j2 & 31; v = w1r[(k * 128 + f) * 32 + h]; }
        g_Wp1[i] = v;
    } else if (i < 20480) {                // Wd1 : 64 x 64 block-diagonal
        int i2 = i - 16384;
        int g = i2 >> 6, h = i2 & 63;
        int kg = g >> 5, kh = h >> 5;
        g_Wd1[i2] = (kg == kh) ? w1d[(kg * 32 + (g & 31)) * 32 + (h & 31)] : 0.0f;
    } else if (i < 25600) {                // Wp2 : 32 x 160
        int i3 = i - 20480;
        int f = i3 / 160, j = i3 % 160;
        float v;
        if (j < 80) { int k = j / 40, h = j % 40; v = w2i[(k * 32 + f) * 40 + h]; }
        else        { int j2 = j - 80; int k = j2 / 40, h = j2 % 40; v = w2r[(k * 32 + f) * 40 + h]; }
        g_Wp2[i3] = v;
    } else if (i < 32000) {                // Wd2 : 80 x 80 block-diagonal
        int i4 = i - 25600;
        int g = i4 / 80, h = i4 % 80;
        int kg = g / 40, kh = h / 40;
        g_Wd2[i4] = (kg == kh) ? w2d[(kg * 40 + (g % 40)) * 40 + (h % 40)] : 0.0f;
    }
}

// ---------------- generic register-tiled GEMM: C[N,J] = X[N,F] @ W[F,J] ----------------
// 64x64 tile per block, 256 threads, 4x4 micro-tile per thread. F must be a multiple of 16.
__global__ void gemm_kernel(const float* __restrict__ X, int ldx,
                            const float* __restrict__ W, int ldw,
                            float* __restrict__ C, int ldc,
                            int nrows, int F, int J) {
    __shared__ float xs[64][17];   // [m][f], padded to dodge bank conflicts
    __shared__ float ws[16][64];   // [f][j]

    const int tid = threadIdx.x;          // 0..255
    const int tx  = tid & 15;             // j micro-tile
    const int ty  = tid >> 4;             // m micro-tile
    const int n0  = blockIdx.x * 64;
    const int j0  = blockIdx.y * 64;

    float acc[4][4] = {};

    for (int f0 = 0; f0 < F; f0 += 16) {
        #pragma unroll
        for (int l = 0; l < 4; ++l) {
            int idx = tid + l * 256;       // 0..1023
            int m = idx >> 4, f = idx & 15;
            int n = n0 + m;
            float v = 0.0f;
            if (n < nrows) v = X[(size_t)n * ldx + f0 + f];
            xs[m][f] = v;
        }
        #pragma unroll
        for (int l = 0; l < 4; ++l) {
            int idx = tid + l * 256;
            int f = idx >> 6, j = idx & 63;
            float v = 0.0f;
            if (j0 + j < J) v = W[(size_t)(f0 + f) * ldw + j0 + j];
            ws[f][j] = v;
        }
        __syncthreads();
        #pragma unroll
        for (int f = 0; f < 16; ++f) {
            float4 wv = *(const float4*)&ws[f][tx * 4];
            float x0 = xs[ty * 4 + 0][f];
            float x1 = xs[ty * 4 + 1][f];
            float x2 = xs[ty * 4 + 2][f];
            float x3 = xs[ty * 4 + 3][f];
            acc[0][0] = fmaf(x0, wv.x, acc[0][0]); acc[0][1] = fmaf(x0, wv.y, acc[0][1]);
            acc[0][2] = fmaf(x0, wv.z, acc[0][2]); acc[0][3] = fmaf(x0, wv.w, acc[0][3]);
            acc[1][0] = fmaf(x1, wv.x, acc[1][0]); acc[1][1] = fmaf(x1, wv.y, acc[1][1]);
            acc[1][2] = fmaf(x1, wv.z, acc[1][2]); acc[1][3] = fmaf(x1, wv.w, acc[1][3]);
            acc[2][0] = fmaf(x2, wv.x, acc[2][0]); acc[2][1] = fmaf(x2, wv.y, acc[2][1]);
            acc[2][2] = fmaf(x2, wv.z, acc[2][2]); acc[2][3] = fmaf(x2, wv.w, acc[2][3]);
            acc[3][0] = fmaf(x3, wv.x, acc[3][0]); acc[3][1] = fmaf(x3, wv.y, acc[3][1]);
            acc[3][2] = fmaf(x3, wv.z, acc[3][2]); acc[3][3] = fmaf(x3, wv.w, acc[3][3]);
        }
        __syncthreads();
    }

    #pragma unroll
    for (int r = 0; r < 4; ++r) {
        int n = n0 + ty * 4 + r;
        if (n >= nrows) continue;
        int jb = j0 + tx * 4;
        if (jb + 3 < J) {
            float4 v = make_float4(acc[r][0], acc[r][1], acc[r][2], acc[r][3]);
            *(float4*)&C[(size_t)n * ldc + jb] = v;
        } else {
            #pragma unroll
            for (int c = 0; c < 4; ++c)
                if (jb + c < J) C[(size_t)n * ldc + jb + c] = acc[r][c];
        }
    }
}

// ---------------- CSR propagate: out[n] = sum_e ew*src[srce] + root[n] + bias (relu / mean) ----
template <int FTOT, bool RELU, bool FINAL>
__global__ void prop_kernel(const float* __restrict__ src, int lds,
                            const float* __restrict__ root, int ldr,
                            const float* __restrict__ bias,
                            float* __restrict__ out, int ldo) {
    const int gwarp = (blockIdx.x * blockDim.x + threadIdx.x) >> 5;
    const int lane  = threadIdx.x & 31;
    const int wwarp = threadIdx.x >> 5;           // 0..7 (blockDim = 256)
    __shared__ float sm[8][FTOT];
    if (gwarp >= NN) return;
    const int n   = gwarp;
    const int beg = g_off[n];
    const int end = g_off[n + 1];

    float a0 = 0.f, a1 = 0.f, a2 = 0.f;
    int e = beg;
    for (; e + 2 <= end; e += 2) {                // 2-edge unroll for MLP
        int   s0 = g_srce[e],   s1 = g_srce[e + 1];
        float w0 = g_ew[e],     w1 = g_ew[e + 1];
        const float* p0 = src + (size_t)s0 * lds;
        const float* p1 = src + (size_t)s1 * lds;
        float u0 = p0[lane],      v0 = p1[lane];
        float u1 = p0[lane + 32], v1 = p1[lane + 32];
        a0 = fmaf(w0, u0, a0); a0 = fmaf(w1, v0, a0);
        a1 = fmaf(w0, u1, a1); a1 = fmaf(w1, v1, a1);
        if (FTOT == 80) {
            if (lane < 16) {
                a2 = fmaf(w0, p0[lane + 64], a2);
                a2 = fmaf(w1, p1[lane + 64], a2);
            }
        }
    }
    if (e < end) {
        int   s0 = g_srce[e];
        float w0 = g_ew[e];
        const float* p0 = src + (size_t)s0 * lds;
        a0 = fmaf(w0, p0[lane], a0);
        a1 = fmaf(w0, p0[lane + 32], a1);
        if (FTOT == 80) { if (lane < 16) a2 = fmaf(w0, p0[lane + 64], a2); }
    }

    const float* rp = root + (size_t)n * ldr;
    float y0 = a0 + rp[lane]      + bias[lane];
    float y1 = a1 + rp[lane + 32] + bias[lane + 32];
    float y2 = 0.f;
    if (FTOT == 80 && lane < 16) y2 = a2 + rp[lane + 64] + bias[lane + 64];
    if (RELU) { y0 = fmaxf(y0, 0.f); y1 = fmaxf(y1, 0.f); y2 = fmaxf(y2, 0.f); }

    if (!FINAL) {
        float* op = out + (size_t)n * ldo;
        op[lane] = y0;
        op[lane + 32] = y1;
        if (FTOT == 80) { if (lane < 16) op[lane + 64] = y2; }
    } else {
        sm[wwarp][lane] = y0;
        sm[wwarp][lane + 32] = y1;
        if (FTOT == 80) { if (lane < 16) sm[wwarp][lane + 64] = y2; }
        __syncwarp();
        if (FTOT == 64) {   // FOUT = 32, stacks at j and j+32
            out[(size_t)n * 32 + lane] = 0.5f * (sm[wwarp][lane] + sm[wwarp][lane + 32]);
        } else {            // FTOT = 80, FOUT = 40, stacks at h and h+40
            out[(size_t)n * 40 + lane] = 0.5f * (sm[wwarp][lane] + sm[wwarp][lane + 40]);
            if (lane < 8)
                out[(size_t)n * 40 + 32 + lane] =
                    0.5f * (sm[wwarp][32 + lane] + sm[wwarp][72 + lane]);
        }
    }
}

// ---------------- log_softmax over 40 classes, warp per node ----------------
__global__ void lsm_kernel(const float* __restrict__ h2, float* __restrict__ out) {
    const int gwarp = (blockIdx.x * blockDim.x + threadIdx.x) >> 5;
    const int lane  = threadIdx.x & 31;
    if (gwarp >= NN) return;
    const float* p = h2 + (size_t)gwarp * 40;
    float v0 = p[lane];
    float v1 = (lane < 8) ? p[32 + lane] : -3.0e38f;
    float m = fmaxf(v0, v1);
    #pragma unroll
    for (int o = 16; o; o >>= 1) m = fmaxf(m, __shfl_xor_sync(0xffffffffu, m, o));
    float s = expf(v0 - m) + ((lane < 8) ? expf(v1 - m) : 0.0f);
    #pragma unroll
    for (int o = 16; o; o >>= 1) s += __shfl_xor_sync(0xffffffffu, s, o);
    float l = m + logf(s);
    float* q = out + (size_t)gwarp * 40;
    q[lane] = v0 - l;
    if (lane < 8) q[32 + lane] = v1 - l;
}

// ---------------- launch ----------------
extern "C" void kernel_launch(void* const* d_in, const int* in_sizes, int n_in,
                              void* d_out, int out_size) {
    const float* x    = (const float*)d_in[0];
    const int*   eidx = (const int*)  d_in[1];
    const float* w1i  = (const float*)d_in[2];
    const float* w1d  = (const float*)d_in[3];
    const float* w1r  = (const float*)d_in[4];
    const float* b1   = (const float*)d_in[5];
    const float* w2i  = (const float*)d_in[6];
    const float* w2d  = (const float*)d_in[7];
    const float* w2r  = (const float*)d_in[8];
    const float* b2   = (const float*)d_in[9];
    float* outp = (float*)d_out;

    const int* row = eidx;
    const int* col = eidx + EE;

    // device-global scratch addresses
    float *A, *B, *C, *H, *D, *E2, *F2, *H2, *Wp1, *Wd1, *Wp2, *Wd2;
    cudaGetSymbolAddress((void**)&A,   g_A);
    cudaGetSymbolAddress((void**)&B,   g_B);
    cudaGetSymbolAddress((void**)&C,   g_C);
    cudaGetSymbolAddress((void**)&H,   g_h);
    cudaGetSymbolAddress((void**)&D,   g_D);
    cudaGetSymbolAddress((void**)&E2,  g_E2);
    cudaGetSymbolAddress((void**)&F2,  g_F2);
    cudaGetSymbolAddress((void**)&H2,  g_h2);
    cudaGetSymbolAddress((void**)&Wp1, g_Wp1);
    cudaGetSymbolAddress((void**)&Wd1, g_Wd1);
    cudaGetSymbolAddress((void**)&Wp2, g_Wp2);
    cudaGetSymbolAddress((void**)&Wd2, g_Wd2);

    const int TB = 256;
    const int nblkN = (NN + TB - 1) / TB;            // 196
    const int nblkE = (EE + TB - 1) / TB;            // 3125
    const int nblkW = (NN * 32 + TB - 1) / TB;       // 6250 (warp per node)
    const dim3 gN64((NN + 63) / 64, 1);

    // graph prep
    zero_deg_kernel<<<nblkN, TB>>>();
    prep_kernel<<<(32000 + TB - 1) / TB, TB>>>(w1i, w1d, w1r, w2i, w2d, w2r);
    hist_kernel<<<nblkE, TB>>>(col);
    dinv_kernel<<<nblkN, TB>>>();
    scan_kernel<<<1, 1024>>>();
    fill_kernel<<<nblkE, TB>>>(row, col);

    // ---- conv1 ----
    gemm_kernel<<<dim3((NN + 63) / 64, 2), TB>>>(x, 128, Wp1, 128, A, 128, NN, 128, 128);
    prop_kernel<64, true, false><<<nblkW, TB>>>(A, 128, A + 64, 128, b1, B, 64);
    gemm_kernel<<<dim3((NN + 63) / 64, 1), TB>>>(B, 64, Wd1, 64, C, 64, NN, 64, 64);
    prop_kernel<64, true, true ><<<nblkW, TB>>>(C, 64, A + 64, 128, b1, H, 32);

    // ---- conv2 ----
    gemm_kernel<<<dim3((NN + 63) / 64, 3), TB>>>(H, 32, Wp2, 160, D, 160, NN, 32, 160);
    prop_kernel<80, false, false><<<nblkW, TB>>>(D, 160, D + 80, 160, b2, E2, 80);
    gemm_kernel<<<dim3((NN + 63) / 64, 2), TB>>>(E2, 80, Wd2, 80, F2, 80, NN, 80, 80);
    prop_kernel<80, false, true ><<<nblkW, TB>>>(F2, 80, D + 80, 160, b2, H2, 40);

    // ---- log_softmax ----
    lsm_kernel<<<nblkW, TB>>>(H2, outp);
}